// round 13
// baseline (speedup 1.0000x reference)
#include <cuda_runtime.h>
#include <math.h>

#define BB 2048
#define TT 2048
#define CC 8
#define AA 27
#define HH 8

__device__ __forceinline__ float tanh_approx(float v) {
    float r;
    asm("tanh.approx.f32 %0, %1;" : "=f"(r) : "f"(v));
    return r;
}

__device__ __forceinline__ float elu(float y) {
    return (y > 0.0f) ? y : expm1f(y);
}

// Fused. Fine-grained blocks (4 per row, 256 threads, 2 t/thread) for wave
// balance; the per-row MLP runs ONCE per block in warp 0 (warp-cooperative,
// shfl-based) into smem, hidden under the other warps' prefetched x loads.
__global__ void __launch_bounds__(256) fused_kernel(
    const float* __restrict__ x,
    const float* __restrict__ attrs,
    const float* __restrict__ w1,  const float* __restrict__ b1,
    const float* __restrict__ w2,  const float* __restrict__ b2,
    const float* __restrict__ bw1, const float* __restrict__ bb1,
    const float* __restrict__ bw2, const float* __restrict__ bb2,
    const float* __restrict__ mask_a,
    const float* __restrict__ mask_h,
    float* __restrict__ out)
{
    __shared__ float sk[CC];
    __shared__ float sbias;

    int tid  = threadIdx.x;
    int wid  = tid >> 5;
    int lane = tid & 31;
    int b    = blockIdx.x >> 2;                        // 4 blocks per row
    int t0   = ((blockIdx.x & 3) << 9) + tid;          // t0 and t0+256

    // ---- prefetch both t's before the MLP/barrier (stays in flight) ----
    const float4* xrow = (const float4*)(x + (long)b * TT * CC);
    float4 xa0 = __ldcs(&xrow[t0 * 2]);
    float4 xa1 = __ldcs(&xrow[t0 * 2 + 1]);
    float4 xb0 = __ldcs(&xrow[(t0 + 256) * 2]);
    float4 xb1 = __ldcs(&xrow[(t0 + 256) * 2 + 1]);

    // ---- warp 0 only: warp-cooperative MLP -> smem ----
    if (wid == 0) {
        const unsigned FULL = 0xFFFFFFFFu;
        int h = lane & 7;
        int g = lane >> 3;

        float hw = 0.0f, hb = 0.0f;
#pragma unroll
        for (int s = 0; s < 7; s++) {
            int i = g + 4 * s;
            if (i < AA) {
                float ai = attrs[b * AA + i] * mask_a[b * AA + i];
                hw = fmaf(ai, w1[i * HH + h], hw);
                hb = fmaf(ai, bw1[i * HH + h], hb);
            }
        }
        hw += __shfl_xor_sync(FULL, hw, 8);
        hw += __shfl_xor_sync(FULL, hw, 16);
        hb += __shfl_xor_sync(FULL, hb, 8);
        hb += __shfl_xor_sync(FULL, hb, 16);

        float m = mask_h[b * HH + h];
        hw = fmaxf(hw + b1[h], 0.0f) * m;
        hb = fmaxf(hb + bb1[h], 0.0f) * m;

        float kacc = b2[h];
        float bacc = bb2[0];
#pragma unroll
        for (int hh = 0; hh < 8; hh++) {
            float hwv = __shfl_sync(FULL, hw, hh);
            float hbv = __shfl_sync(FULL, hb, hh);
            kacc = fmaf(hwv, w2[hh * CC + h], kacc);
            bacc = fmaf(hbv, bw2[hh], bacc);
        }
        float kc = tanh_approx(kacc);
        if (lane < 8)  sk[lane] = kc;
        if (lane == 0) sbias = tanh_approx(bacc);
    }
    __syncthreads();

    float k0 = sk[0], k1 = sk[1], k2 = sk[2], k3 = sk[3];
    float k4 = sk[4], k5 = sk[5], k6 = sk[6], k7 = sk[7];
    float bias = sbias;

    // ---- contraction + ELU for both t's ----
    float ya = bias;
    ya = fmaf(xa0.x, k0, ya); ya = fmaf(xa0.y, k1, ya);
    ya = fmaf(xa0.z, k2, ya); ya = fmaf(xa0.w, k3, ya);
    ya = fmaf(xa1.x, k4, ya); ya = fmaf(xa1.y, k5, ya);
    ya = fmaf(xa1.z, k6, ya); ya = fmaf(xa1.w, k7, ya);

    float yb = bias;
    yb = fmaf(xb0.x, k0, yb); yb = fmaf(xb0.y, k1, yb);
    yb = fmaf(xb0.z, k2, yb); yb = fmaf(xb0.w, k3, yb);
    yb = fmaf(xb1.x, k4, yb); yb = fmaf(xb1.y, k5, yb);
    yb = fmaf(xb1.z, k6, yb); yb = fmaf(xb1.w, k7, yb);

    long base = (long)b * TT + t0;
    __stcs(&out[base],       elu(ya));
    __stcs(&out[base + 256], elu(yb));
}

extern "C" void kernel_launch(void* const* d_in, const int* in_sizes, int n_in,
                              void* d_out, int out_size) {
    const float* x      = (const float*)d_in[0];
    const float* attrs  = (const float*)d_in[1];
    const float* w1     = (const float*)d_in[2];
    const float* b1     = (const float*)d_in[3];
    const float* w2     = (const float*)d_in[4];
    const float* b2     = (const float*)d_in[5];
    const float* bw1    = (const float*)d_in[6];
    const float* bb1    = (const float*)d_in[7];
    const float* bw2    = (const float*)d_in[8];
    const float* bb2    = (const float*)d_in[9];
    const float* mask_a = (const float*)d_in[10];
    const float* mask_h = (const float*)d_in[11];
    float* out = (float*)d_out;

    fused_kernel<<<BB * 4, 256>>>(x, attrs, w1, b1, w2, b2,
                                  bw1, bb1, bw2, bb2,
                                  mask_a, mask_h, out);
}